// round 5
// baseline (speedup 1.0000x reference)
#include <cuda_runtime.h>
#include <cuda_fp16.h>
#include <cstdint>

// Problem dims (LLaMA-7B up-proj, AWQ w4 g128)
#define O_DIM 11008
#define I_DIM 4096
#define M_DIM 8192   // B*S
#define X_ELEMS ((size_t)M_DIM * I_DIM)

// GEMM tiling
#define BM 128
#define BN 128
#define BK 32
#define KT (I_DIM / BK)   // 128
#define PAD 8

// Scratch: dequantized weights (O,I) fp16, staged activations (M,K) fp16
static __device__ __half g_W[(size_t)O_DIM * I_DIM];
static __device__ __half g_x[X_ELEMS];
static __device__ int    g_swap;  // 1 if s1 is adjusted_zeros

// ---------------------------------------------------------------------------
// Probe: adjusted_zeros = -(scale*zp) -> sign bit always set (incl -0.0);
// scales strictly positive -> sign bit never set.
// ---------------------------------------------------------------------------
__global__ void probe_kernel(const uint32_t* __restrict__ s1w) {
    __shared__ int cnt;
    if (threadIdx.x == 0) cnt = 0;
    __syncthreads();
    int c = 0;
    for (int i = threadIdx.x; i < 4096; i += 256)
        if (s1w[i] & 0x80000000u) c++;
    atomicAdd(&cnt, c);
    __syncthreads();
    if (threadIdx.x == 0) g_swap = (cnt > 2048) ? 1 : 0;
}

// ---------------------------------------------------------------------------
// Stage x: fp32 (exact fp16 upcasts) -> fp16, lossless
// ---------------------------------------------------------------------------
__global__ void stage_x_kernel(const float* __restrict__ xin) {
    size_t i = ((size_t)blockIdx.x * blockDim.x + threadIdx.x) * 8;
    if (i >= X_ELEMS) return;
    const float4* p = (const float4*)(xin + i);
    float4 a = p[0], b = p[1];
    __half h[8] = {__float2half(a.x), __float2half(a.y), __float2half(a.z), __float2half(a.w),
                   __float2half(b.x), __float2half(b.y), __float2half(b.z), __float2half(b.w)};
    *(uint4*)(g_x + i) = *(const uint4*)h;
}

// ---------------------------------------------------------------------------
// Dequantize AWQ int4 -> fp16 W[o][i]
// For original col j in a 32-block: permuted jp = 8*((j>>1)&3)+4*(j&1)+(j>>3);
// packed word offset (o&3)*16 + (iblk&1)*8 + (jp>>2), nibble (jp&3) = j>>3.
// ---------------------------------------------------------------------------
__global__ void dequant_kernel(const int* __restrict__ packed,
                               const float* __restrict__ s1,
                               const float* __restrict__ s2) {
    int gid = blockIdx.x * blockDim.x + threadIdx.x;
    int o    = gid >> 7;
    int iblk = gid & 127;
    if (o >= O_DIM) return;
    const float* sf = g_swap ? s2 : s1;
    const float* az = g_swap ? s1 : s2;

    int r = o >> 2;
    int a = o & 3;
    const int* p = packed + (size_t)r * I_DIM + (iblk >> 1) * 64 + a * 16 + (iblk & 1) * 8;
    int4 w0 = *(const int4*)p;
    int4 w1 = *(const int4*)(p + 4);
    int regs[8] = {w0.x, w0.y, w0.z, w0.w, w1.x, w1.y, w1.z, w1.w};

    int g = iblk >> 2;
    float scale = sf[(size_t)g * O_DIM + o];
    float zero  = az[(size_t)g * O_DIM + o];

    __half out[32];
#pragma unroll
    for (int c = 0; c < 32; ++c) {
        int reg = ((c >> 1) & 3) * 2 + (c & 1);
        int nib = (regs[reg] >> ((c >> 3) * 4)) & 15;
        out[c] = __float2half(fmaf((float)nib, scale, zero));
    }

    uint4* dst = (uint4*)(g_W + (size_t)o * I_DIM + iblk * 32);
    const uint4* src = (const uint4*)out;
    dst[0] = src[0]; dst[1] = src[1]; dst[2] = src[2]; dst[3] = src[3];
}

// ---------------------------------------------------------------------------
// GEMM: out[m,n] = fp16(sum_k x[m,k]*W[n,k]) + fp16(bias[n]), stored as fp32
// ---------------------------------------------------------------------------
__device__ __forceinline__ uint32_t smem_u32(const void* p) {
    return (uint32_t)__cvta_generic_to_shared(p);
}
__device__ __forceinline__ void cp_async16(void* dst, const void* src) {
    asm volatile("cp.async.cg.shared.global [%0], [%1], 16;\n"
                 :: "r"(smem_u32(dst)), "l"(src));
}
__device__ __forceinline__ void ldsm_x4(uint32_t& r0, uint32_t& r1, uint32_t& r2, uint32_t& r3,
                                        const void* p) {
    asm volatile("ldmatrix.sync.aligned.m8n8.x4.shared.b16 {%0,%1,%2,%3}, [%4];\n"
                 : "=r"(r0), "=r"(r1), "=r"(r2), "=r"(r3) : "r"(smem_u32(p)));
}
__device__ __forceinline__ void ldsm_x2(uint32_t& r0, uint32_t& r1, const void* p) {
    asm volatile("ldmatrix.sync.aligned.m8n8.x2.shared.b16 {%0,%1}, [%2];\n"
                 : "=r"(r0), "=r"(r1) : "r"(smem_u32(p)));
}
__device__ __forceinline__ void mma16816(float& c0, float& c1, float& c2, float& c3,
                                         uint32_t a0, uint32_t a1, uint32_t a2, uint32_t a3,
                                         uint32_t b0, uint32_t b1) {
    asm volatile("mma.sync.aligned.m16n8k16.row.col.f32.f16.f16.f32 "
                 "{%0,%1,%2,%3}, {%4,%5,%6,%7}, {%8,%9}, {%0,%1,%2,%3};\n"
                 : "+f"(c0), "+f"(c1), "+f"(c2), "+f"(c3)
                 : "r"(a0), "r"(a1), "r"(a2), "r"(a3), "r"(b0), "r"(b1));
}

__global__ void __launch_bounds__(256)
gemm_kernel(const float* __restrict__ bias_in, float* __restrict__ out) {
    __shared__ __align__(16) __half Ash[2][BM][BK + PAD];
    __shared__ __align__(16) __half Bsh[2][BN][BK + PAD];

    const int tid  = threadIdx.x;
    const int lane = tid & 31;
    const int wid  = tid >> 5;
    const int wm   = wid & 1;
    const int wn   = wid >> 1;

    const int m0 = blockIdx.y * BM;
    const int n0 = blockIdx.x * BN;

    float acc[4][4][4];
#pragma unroll
    for (int i = 0; i < 4; ++i)
#pragma unroll
        for (int j = 0; j < 4; ++j)
#pragma unroll
            for (int k = 0; k < 4; ++k) acc[i][j][k] = 0.0f;

    auto load_tiles = [&](int kt, int buf) {
        int k0 = kt * BK;
#pragma unroll
        for (int l = 0; l < 2; ++l) {
            int idx = tid + l * 256;
            int row = idx >> 2;
            int cc  = idx & 3;
            cp_async16(&Ash[buf][row][cc * 8],
                       g_x + (size_t)(m0 + row) * I_DIM + k0 + cc * 8);
            cp_async16(&Bsh[buf][row][cc * 8],
                       g_W + (size_t)(n0 + row) * I_DIM + k0 + cc * 8);
        }
    };

    load_tiles(0, 0);
    asm volatile("cp.async.commit_group;\n");

    for (int kt = 0; kt < KT; ++kt) {
        int buf = kt & 1;
        if (kt + 1 < KT) {
            load_tiles(kt + 1, (kt + 1) & 1);
            asm volatile("cp.async.commit_group;\n");
            asm volatile("cp.async.wait_group 1;\n");
        } else {
            asm volatile("cp.async.wait_group 0;\n");
        }
        __syncthreads();

#pragma unroll
        for (int ks = 0; ks < BK / 16; ++ks) {
            uint32_t a[4][4];
#pragma unroll
            for (int mt = 0; mt < 4; ++mt) {
                const __half* p = &Ash[buf][wm * 64 + mt * 16 + (lane & 15)]
                                       [ks * 16 + (lane >> 4) * 8];
                ldsm_x4(a[mt][0], a[mt][1], a[mt][2], a[mt][3], p);
            }
            uint32_t b[4][2];
#pragma unroll
            for (int nt = 0; nt < 4; ++nt) {
                const __half* p = &Bsh[buf][wn * 32 + nt * 8 + (lane & 7)]
                                       [ks * 16 + ((lane >> 3) & 1) * 8];
                ldsm_x2(b[nt][0], b[nt][1], p);
            }
#pragma unroll
            for (int mt = 0; mt < 4; ++mt)
#pragma unroll
                for (int nt = 0; nt < 4; ++nt)
                    mma16816(acc[mt][nt][0], acc[mt][nt][1], acc[mt][nt][2], acc[mt][nt][3],
                             a[mt][0], a[mt][1], a[mt][2], a[mt][3],
                             b[nt][0], b[nt][1]);
        }
        __syncthreads();
    }

    // Epilogue: round acc to fp16, add fp16(bias) in fp16, upcast to fp32 store
#pragma unroll
    for (int mt = 0; mt < 4; ++mt) {
#pragma unroll
        for (int nt = 0; nt < 4; ++nt) {
            int m = m0 + wm * 64 + mt * 16 + (lane >> 2);
            int n = n0 + wn * 32 + nt * 8 + (lane & 3) * 2;
            __half b0h = __float2half(bias_in[n]);
            __half b1h = __float2half(bias_in[n + 1]);
            __half r00 = __hadd(__float2half(acc[mt][nt][0]), b0h);
            __half r01 = __hadd(__float2half(acc[mt][nt][1]), b1h);
            __half r10 = __hadd(__float2half(acc[mt][nt][2]), b0h);
            __half r11 = __hadd(__float2half(acc[mt][nt][3]), b1h);
            *(float2*)(out + (size_t)m * O_DIM + n) =
                make_float2(__half2float(r00), __half2float(r01));
            *(float2*)(out + (size_t)(m + 8) * O_DIM + n) =
                make_float2(__half2float(r10), __half2float(r11));
        }
    }
}

// ---------------------------------------------------------------------------
extern "C" void kernel_launch(void* const* d_in, const int* in_sizes, int n_in,
                              void* d_out, int out_size) {
    // Slot inputs by size rank (unit-agnostic): x > packed > {scales,zeros} > bias
    long long sz[16];
    int used[16], order[16];
    for (int i = 0; i < n_in && i < 16; ++i) { sz[i] = in_sizes[i]; used[i] = 0; }
    for (int r = 0; r < n_in && r < 16; ++r) {
        int best = -1;
        for (int i = 0; i < n_in && i < 16; ++i)
            if (!used[i] && (best < 0 || sz[i] > sz[best])) best = i;
        used[best] = 1;
        order[r] = best;
    }
    const float* x      = (const float*)d_in[order[0]];
    const int*   packed = (const int*)d_in[order[1]];
    const float* s1     = (const float*)d_in[order[2]];
    const float* s2     = (const float*)d_in[order[3]];
    const float* bias   = (const float*)d_in[order[n_in < 5 ? n_in - 1 : 4]];

    probe_kernel<<<1, 256>>>((const uint32_t*)s1);
    stage_x_kernel<<<(int)(X_ELEMS / 8 / 256), 256>>>(x);
    dequant_kernel<<<(O_DIM * (I_DIM / 32)) / 256, 256>>>(packed, s1, s2);

    dim3 grid(O_DIM / BN, M_DIM / BM);  // (86, 64)
    gemm_kernel<<<grid, 256>>>(bias, (float*)d_out);
}

// round 7
// speedup vs baseline: 1.0280x; 1.0280x over previous
#include <cuda_runtime.h>
#include <cuda_fp16.h>
#include <cstdint>

// Problem dims (LLaMA-7B up-proj, AWQ w4 g128)
#define O_DIM 11008
#define I_DIM 4096
#define M_DIM 8192   // B*S
#define X_ELEMS ((size_t)M_DIM * I_DIM)

// GEMM tiling
#define BM 128
#define BN 128
#define BK 32
#define KT (I_DIM / BK)   // 128
#define PAD 8
#define STAGES 4

// Scratch: dequantized weights (O,I) fp16, staged activations (M,K) fp16
static __device__ __half g_W[(size_t)O_DIM * I_DIM];
static __device__ __half g_x[X_ELEMS];
static __device__ int    g_swap;  // 1 if s1 is adjusted_zeros

// ---------------------------------------------------------------------------
// Probe: adjusted_zeros = -(scale*zp) -> sign bit always set (incl -0.0)
// ---------------------------------------------------------------------------
__global__ void probe_kernel(const uint32_t* __restrict__ s1w) {
    __shared__ int cnt;
    if (threadIdx.x == 0) cnt = 0;
    __syncthreads();
    int c = 0;
    for (int i = threadIdx.x; i < 4096; i += 256)
        if (s1w[i] & 0x80000000u) c++;
    atomicAdd(&cnt, c);
    __syncthreads();
    if (threadIdx.x == 0) g_swap = (cnt > 2048) ? 1 : 0;
}

// ---------------------------------------------------------------------------
// Stage x: fp32 (exact fp16 upcasts) -> fp16, lossless
// ---------------------------------------------------------------------------
__global__ void stage_x_kernel(const float* __restrict__ xin) {
    size_t i = ((size_t)blockIdx.x * blockDim.x + threadIdx.x) * 8;
    if (i >= X_ELEMS) return;
    const float4* p = (const float4*)(xin + i);
    float4 a = p[0], b = p[1];
    __half h[8] = {__float2half(a.x), __float2half(a.y), __float2half(a.z), __float2half(a.w),
                   __float2half(b.x), __float2half(b.y), __float2half(b.z), __float2half(b.w)};
    *(uint4*)(g_x + i) = *(const uint4*)h;
}

// ---------------------------------------------------------------------------
// Dequantize AWQ int4 -> fp16 W[o][i]
// ---------------------------------------------------------------------------
__global__ void dequant_kernel(const int* __restrict__ packed,
                               const float* __restrict__ s1,
                               const float* __restrict__ s2) {
    int gid = blockIdx.x * blockDim.x + threadIdx.x;
    int o    = gid >> 7;
    int iblk = gid & 127;
    if (o >= O_DIM) return;
    const float* sf = g_swap ? s2 : s1;
    const float* az = g_swap ? s1 : s2;

    int r = o >> 2;
    int a = o & 3;
    const int* p = packed + (size_t)r * I_DIM + (iblk >> 1) * 64 + a * 16 + (iblk & 1) * 8;
    int4 w0 = *(const int4*)p;
    int4 w1 = *(const int4*)(p + 4);
    int regs[8] = {w0.x, w0.y, w0.z, w0.w, w1.x, w1.y, w1.z, w1.w};

    int g = iblk >> 2;
    float scale = sf[(size_t)g * O_DIM + o];
    float zero  = az[(size_t)g * O_DIM + o];

    __half out[32];
#pragma unroll
    for (int c = 0; c < 32; ++c) {
        int reg = ((c >> 1) & 3) * 2 + (c & 1);
        int nib = (regs[reg] >> ((c >> 3) * 4)) & 15;
        out[c] = __float2half(fmaf((float)nib, scale, zero));
    }

    uint4* dst = (uint4*)(g_W + (size_t)o * I_DIM + iblk * 32);
    const uint4* src = (const uint4*)out;
    dst[0] = src[0]; dst[1] = src[1]; dst[2] = src[2]; dst[3] = src[3];
}

// ---------------------------------------------------------------------------
// GEMM: out[m,n] = fp16(sum_k x[m,k]*W[n,k]) + fp16(bias[n]), stored as fp32
// 128x128x32 tiles, 4-stage cp.async pipeline, ONE barrier per k-tile.
// ---------------------------------------------------------------------------
__device__ __forceinline__ uint32_t smem_u32(const void* p) {
    return (uint32_t)__cvta_generic_to_shared(p);
}
__device__ __forceinline__ void cp_async16(void* dst, const void* src) {
    asm volatile("cp.async.cg.shared.global [%0], [%1], 16;\n"
                 :: "r"(smem_u32(dst)), "l"(src));
}
__device__ __forceinline__ void ldsm_x4(uint32_t& r0, uint32_t& r1, uint32_t& r2, uint32_t& r3,
                                        const void* p) {
    asm volatile("ldmatrix.sync.aligned.m8n8.x4.shared.b16 {%0,%1,%2,%3}, [%4];\n"
                 : "=r"(r0), "=r"(r1), "=r"(r2), "=r"(r3) : "r"(smem_u32(p)));
}
__device__ __forceinline__ void ldsm_x2(uint32_t& r0, uint32_t& r1, const void* p) {
    asm volatile("ldmatrix.sync.aligned.m8n8.x2.shared.b16 {%0,%1}, [%2];\n"
                 : "=r"(r0), "=r"(r1) : "r"(smem_u32(p)));
}
__device__ __forceinline__ void mma16816(float& c0, float& c1, float& c2, float& c3,
                                         uint32_t a0, uint32_t a1, uint32_t a2, uint32_t a3,
                                         uint32_t b0, uint32_t b1) {
    asm volatile("mma.sync.aligned.m16n8k16.row.col.f32.f16.f16.f32 "
                 "{%0,%1,%2,%3}, {%4,%5,%6,%7}, {%8,%9}, {%0,%1,%2,%3};\n"
                 : "+f"(c0), "+f"(c1), "+f"(c2), "+f"(c3)
                 : "r"(a0), "r"(a1), "r"(a2), "r"(a3), "r"(b0), "r"(b1));
}

__global__ void __launch_bounds__(256, 2)
gemm_kernel(const float* __restrict__ bias_in, float* __restrict__ out) {
    __shared__ __align__(16) __half Ash[STAGES][BM][BK + PAD];
    __shared__ __align__(16) __half Bsh[STAGES][BN][BK + PAD];

    const int tid  = threadIdx.x;
    const int lane = tid & 31;
    const int wid  = tid >> 5;
    const int wm   = wid & 1;
    const int wn   = wid >> 1;

    const int m0 = blockIdx.y * BM;
    const int n0 = blockIdx.x * BN;

    float acc[4][4][4];
#pragma unroll
    for (int i = 0; i < 4; ++i)
#pragma unroll
        for (int j = 0; j < 4; ++j)
#pragma unroll
            for (int k = 0; k < 4; ++k) acc[i][j][k] = 0.0f;

    auto load_tiles = [&](int kt, int buf) {
        int k0 = kt * BK;
#pragma unroll
        for (int l = 0; l < 2; ++l) {
            int idx = tid + l * 256;
            int row = idx >> 2;
            int cc  = idx & 3;
            cp_async16(&Ash[buf][row][cc * 8],
                       g_x + (size_t)(m0 + row) * I_DIM + k0 + cc * 8);
            cp_async16(&Bsh[buf][row][cc * 8],
                       g_W + (size_t)(n0 + row) * I_DIM + k0 + cc * 8);
        }
    };

    // Prologue: fill stages 0..2
#pragma unroll
    for (int s = 0; s < STAGES - 1; ++s) {
        load_tiles(s, s);
        asm volatile("cp.async.commit_group;\n");
    }

    for (int kt = 0; kt < KT; ++kt) {
        const int buf = kt & (STAGES - 1);
        // Ensure stage kt is resident (keep 2 younger groups in flight)
        asm volatile("cp.async.wait_group %0;\n" :: "n"(STAGES - 2));
        __syncthreads();

        // Issue loads for stage kt+3 into the buffer consumed at kt-1
        if (kt + STAGES - 1 < KT)
            load_tiles(kt + STAGES - 1, (kt + STAGES - 1) & (STAGES - 1));
        asm volatile("cp.async.commit_group;\n");

#pragma unroll
        for (int ks = 0; ks < BK / 16; ++ks) {
            uint32_t a[4][4];
#pragma unroll
            for (int mt = 0; mt < 4; ++mt) {
                const __half* p = &Ash[buf][wm * 64 + mt * 16 + (lane & 15)]
                                       [ks * 16 + (lane >> 4) * 8];
                ldsm_x4(a[mt][0], a[mt][1], a[mt][2], a[mt][3], p);
            }
            uint32_t b[4][2];
#pragma unroll
            for (int nt = 0; nt < 4; ++nt) {
                const __half* p = &Bsh[buf][wn * 32 + nt * 8 + (lane & 7)]
                                       [ks * 16 + ((lane >> 3) & 1) * 8];
                ldsm_x2(b[nt][0], b[nt][1], p);
            }
#pragma unroll
            for (int mt = 0; mt < 4; ++mt)
#pragma unroll
                for (int nt = 0; nt < 4; ++nt)
                    mma16816(acc[mt][nt][0], acc[mt][nt][1], acc[mt][nt][2], acc[mt][nt][3],
                             a[mt][0], a[mt][1], a[mt][2], a[mt][3],
                             b[nt][0], b[nt][1]);
        }
    }

    // Epilogue: round acc to fp16, add fp16(bias) in fp16, upcast to fp32 store
#pragma unroll
    for (int mt = 0; mt < 4; ++mt) {
#pragma unroll
        for (int nt = 0; nt < 4; ++nt) {
            int m = m0 + wm * 64 + mt * 16 + (lane >> 2);
            int n = n0 + wn * 32 + nt * 8 + (lane & 3) * 2;
            __half b0h = __float2half(bias_in[n]);
            __half b1h = __float2half(bias_in[n + 1]);
            __half r00 = __hadd(__float2half(acc[mt][nt][0]), b0h);
            __half r01 = __hadd(__float2half(acc[mt][nt][1]), b1h);
            __half r10 = __hadd(__float2half(acc[mt][nt][2]), b0h);
            __half r11 = __hadd(__float2half(acc[mt][nt][3]), b1h);
            *(float2*)(out + (size_t)m * O_DIM + n) =
                make_float2(__half2float(r00), __half2float(r01));
            *(float2*)(out + (size_t)(m + 8) * O_DIM + n) =
                make_float2(__half2float(r10), __half2float(r11));
        }
    }
}

// ---------------------------------------------------------------------------
extern "C" void kernel_launch(void* const* d_in, const int* in_sizes, int n_in,
                              void* d_out, int out_size) {
    // Slot inputs by size rank (unit-agnostic): x > packed > {scales,zeros} > bias
    long long sz[16];
    int used[16], order[16];
    for (int i = 0; i < n_in && i < 16; ++i) { sz[i] = in_sizes[i]; used[i] = 0; }
    for (int r = 0; r < n_in && r < 16; ++r) {
        int best = -1;
        for (int i = 0; i < n_in && i < 16; ++i)
            if (!used[i] && (best < 0 || sz[i] > sz[best])) best = i;
        used[best] = 1;
        order[r] = best;
    }
    const float* x      = (const float*)d_in[order[0]];
    const int*   packed = (const int*)d_in[order[1]];
    const float* s1     = (const float*)d_in[order[2]];
    const float* s2     = (const float*)d_in[order[3]];
    const float* bias   = (const float*)d_in[order[n_in < 5 ? n_in - 1 : 4]];

    probe_kernel<<<1, 256>>>((const uint32_t*)s1);
    stage_x_kernel<<<(int)(X_ELEMS / 8 / 256), 256>>>(x);
    dequant_kernel<<<(O_DIM * (I_DIM / 32)) / 256, 256>>>(packed, s1, s2);

    dim3 grid(O_DIM / BN, M_DIM / BM);  // (86, 64)
    gemm_kernel<<<grid, 256>>>(bias, (float*)d_out);
}